// round 11
// baseline (speedup 1.0000x reference)
#include <cuda_runtime.h>
#include <cstdint>

#define B_  2
#define N_  4
#define D_  48
#define H_  28
#define W_  60
#define C_  64
#define NX_ 192
#define NY_ 192
// NZ = 1

// Scratch accumulator in C-contiguous layout (B, NY, NX, C) so vector reds work.
// Zero-initialized at module load; transpose_kernel restores it to zero every
// launch, so the zero-at-entry invariant holds across graph replays.
__device__ float g_scratch[B_ * NY_ * NX_ * C_];

// Vectorized fire-and-forget reduction (sm_90+): one 16B red per sub-lane.
__device__ __forceinline__ void red_add_v4(float* addr, float4 v) {
    asm volatile("red.global.add.v4.f32 [%0], {%1, %2, %3, %4};"
                 :: "l"(addr), "f"(v.x), "f"(v.y), "f"(v.z), "f"(v.w)
                 : "memory");
}

// ---------------------------------------------------------------------------
// Per-block geometry setup (folded — replaces the former 1-block setup kernel
// that measured 5.8us of pure launch/ramp in R8's profile).
// Thread i<8 computes combine = pose_rot @ inv(K) and trans for (b,n)=i into
// SMEM. Exact reference fp32 chain (same fmaf order as the passing kernels).
// ---------------------------------------------------------------------------
__device__ __forceinline__ void compute_geo(const float* __restrict__ intr,
                                            const float* __restrict__ pose,
                                            int i, float* __restrict__ geo12) {
    const float* K = intr + i * 9;
    const float* P = pose + i * 16;

    float a = K[0], bb = K[1], c = K[2];
    float d = K[3], e  = K[4], f = K[5];
    float g = K[6], h  = K[7], ii = K[8];

    float A0 = e * ii - f * h;
    float A1 = f * g  - d * ii;
    float A2 = d * h  - e * g;
    float det = a * A0 + bb * A1 + c * A2;

    float inv[9];
    inv[0] = A0 / det;             inv[1] = (c * h - bb * ii) / det; inv[2] = (bb * f - c * e) / det;
    inv[3] = A1 / det;             inv[4] = (a * ii - c * g) / det;  inv[5] = (c * d - a * f) / det;
    inv[6] = A2 / det;             inv[7] = (bb * g - a * h) / det;  inv[8] = (a * e - bb * d) / det;

    for (int r = 0; r < 3; r++) {
        for (int j = 0; j < 3; j++) {
            float s = P[r * 4 + 0] * inv[0 * 3 + j];
            s = fmaf(P[r * 4 + 1], inv[1 * 3 + j], s);
            s = fmaf(P[r * 4 + 2], inv[2 * 3 + j], s);
            geo12[r * 3 + j] = s;
        }
        geo12[9 + r] = P[r * 4 + 3];
    }
}

// ---------------------------------------------------------------------------
// Scatter: one HALF-warp (16 lanes) per (b,d,h,w) group; sub-lane owns 4
// channels.
// Phase 0: threads 0-7 build the 8 view matrices in SMEM; one barrier.
// Phase 1: compute all 4 view flats (pure ALU — exact reference fp32 chain).
// Phase 2: issue all 4 predicated LDG.128s into independent registers (MLP=4;
//          culled views/depths load nothing).
// Phase 3: register-merge consecutive views hitting the same voxel
//          (data-driven flat==cur check), flush via red.global.add.v4.
// Grid is exactly NG*16/256 = 20160 full blocks (no tail-barrier hazard).
// ---------------------------------------------------------------------------
__global__ void __launch_bounds__(256)
scatter_kernel(const float* __restrict__ x,
               const float* __restrict__ intr,
               const float* __restrict__ pose) {
    __shared__ float s_geo[B_ * N_ * 12];

    if (threadIdx.x < B_ * N_)
        compute_geo(intr, pose, threadIdx.x, s_geo + threadIdx.x * 12);
    __syncthreads();

    int tid   = blockIdx.x * blockDim.x + threadIdx.x;
    int group = tid >> 4;                       // one group per 16 lanes
    int sub   = threadIdx.x & 15;               // channel sub-lane
    const int NG = B_ * D_ * H_ * W_;
    if (group >= NG) return;

    int w = group % W_;
    int t = group / W_;
    int h = t % H_;  t /= H_;
    int d = t % D_;
    int b = t / D_;

    float df = 2.0f + (float)d;                 // ds = arange(2,50,1)
    float u  = (float)w * (479.0f / 59.0f);     // linspace(0, 479, 60)
    float v  = (float)h * (223.0f / 27.0f);     // linspace(0, 223, 28)
    float p0 = u * df, p1 = v * df, p2 = df;

    // ---- Phase 1: flats for all 4 views (no memory traffic) ----
    int flat[N_];
    #pragma unroll
    for (int n = 0; n < N_; n++) {
        const float* G = s_geo + (b * N_ + n) * 12;
        float dx = G[0] * p0; dx = fmaf(G[1], p1, dx); dx = fmaf(G[2], p2, dx);
        float dy = G[3] * p0; dy = fmaf(G[4], p1, dy); dy = fmaf(G[5], p2, dy);
        float dz = G[6] * p0; dz = fmaf(G[7], p1, dz); dz = fmaf(G[8], p2, dz);
        float gxf = dx + G[9];
        float gyf = dy + G[10];
        float gzf = dz + G[11];

        // Truncation toward zero == jnp astype(int32); (-0.5 -> 0 is KEPT in both)
        int gx = (int)(gxf * 4.0f + 96.0f);
        int gy = (int)(gyf * 4.0f + 96.0f);
        int gz = (int)__fdiv_rn(gzf + 10.0f, 20.0f);

        flat[n] = -1;
        if (gx >= 0 && gx < NX_ && gy >= 0 && gy < NY_ && gz >= 0 && gz < 1)
            flat[n] = ((b /*NZ=1*/ + gz) * NY_ + gy) * NX_ + gx;
    }

    // ---- Phase 2: hoisted, predicated, independent LDG.128s (MLP=4) ----
    const float* xb = x
        + ((((size_t)b * N_ + 0) * D_ + d) * H_ + h) * (size_t)(W_ * C_)
        + (size_t)w * C_ + sub * 4;

    float4 xv[N_];
    #pragma unroll
    for (int n = 0; n < N_; n++) {
        if (flat[n] >= 0)
            xv[n] = *(const float4*)(xb + (size_t)n * (D_ * H_ * W_ * C_));
    }

    // ---- Phase 3: merge + flush ----
    int    cur = -1;
    float4 acc = make_float4(0.f, 0.f, 0.f, 0.f);
    #pragma unroll
    for (int n = 0; n < N_; n++) {
        if (flat[n] >= 0) {
            if (flat[n] == cur) {
                acc.x += xv[n].x; acc.y += xv[n].y;
                acc.z += xv[n].z; acc.w += xv[n].w;
            } else {
                if (cur >= 0)
                    red_add_v4(g_scratch + (size_t)cur * C_ + sub * 4, acc);
                cur = flat[n]; acc = xv[n];
            }
        }
    }
    if (cur >= 0)
        red_add_v4(g_scratch + (size_t)cur * C_ + sub * 4, acc);
}

// ---------------------------------------------------------------------------
// Transpose scratch (B,NY,NX,C) -> out (B, C, NY, NX), and restore scratch to
// zero for the next replay (replaces a standalone zero kernel). Validated in
// R8 (passed, rel_err 2.8e-7).
// float4 reads, float4 zero-writeback, float4 coalesced out-stores
// (4 x 128B segments per warp instruction; LDS pattern is bank-conflict-free).
// ---------------------------------------------------------------------------
__global__ void transpose_kernel(float* __restrict__ out) {
    __shared__ float s[32][C_ + 1];
    int tile = blockIdx.x;                    // B * NY * (NX/32) = 2304
    int xt = tile % (NX_ / 32);
    int y  = (tile / (NX_ / 32)) % NY_;
    int b  = tile / ((NX_ / 32) * NY_);

    float4* src = (float4*)(g_scratch
        + (((size_t)b * NY_ + y) * NX_ + (size_t)xt * 32) * C_);

    int t = threadIdx.x;                      // 256 threads; 512 float4 per tile
    #pragma unroll
    for (int k = 0; k < 2; k++) {
        int i = t + k * 256;
        float4 val = src[i];
        src[i] = make_float4(0.f, 0.f, 0.f, 0.f);   // self-restore scratch
        int xx = i >> 4;                      // / (C_/4)
        int cc = (i & 15) << 2;
        s[xx][cc + 0] = val.x; s[xx][cc + 1] = val.y;
        s[xx][cc + 2] = val.z; s[xx][cc + 3] = val.w;
    }
    __syncthreads();

    size_t obase = ((size_t)b * C_) * (NY_ * NX_) + (size_t)y * NX_
                 + (size_t)xt * 32;
    #pragma unroll
    for (int k = 0; k < 2; k++) {
        int p  = t + k * 256;                 // 512 (c, x-quad) pairs
        int x4 = (p & 7) * 4;                 // octet of lanes -> 128B run in x
        int c  = p >> 3;
        float4 v = make_float4(s[x4 + 0][c], s[x4 + 1][c],
                               s[x4 + 2][c], s[x4 + 3][c]);
        *(float4*)(out + obase + (size_t)c * (NY_ * NX_) + x4) = v;
    }
}

// ---------------------------------------------------------------------------
extern "C" void kernel_launch(void* const* d_in, const int* in_sizes, int n_in,
                              void* d_out, int out_size) {
    // Resolve inputs by element count (robust to metadata ordering):
    //   x: B*N*D*H*W*C = 41,287,680   pose: B*N*16 = 128   intrinsics: B*N*9 = 72
    const float* x    = nullptr;
    const float* intr = nullptr;
    const float* pose = nullptr;
    for (int i = 0; i < n_in; i++) {
        if (in_sizes[i] == B_ * N_ * 16)      pose = (const float*)d_in[i];
        else if (in_sizes[i] == B_ * N_ * 9)  intr = (const float*)d_in[i];
        else                                  x    = (const float*)d_in[i];
    }
    float* out = (float*)d_out;

    const int ngroups  = B_ * D_ * H_ * W_;      // 322,560 half-warp groups
    const int nthreads = ngroups * 16;           // exactly 20160 blocks of 256
    scatter_kernel<<<nthreads / 256, 256>>>(x, intr, pose);

    transpose_kernel<<<B_ * NY_ * (NX_ / 32), 256>>>(out);
}

// round 15
// speedup vs baseline: 1.3919x; 1.3919x over previous
#include <cuda_runtime.h>
#include <cstdint>

#define B_  2
#define N_  4
#define D_  48
#define H_  28
#define W_  60
#define C_  64
#define NX_ 192
#define NY_ 192
// NZ = 1

// Scratch accumulator in C-contiguous layout (B, NY, NX, C) so vector reds work.
__device__ float g_scratch[B_ * NY_ * NX_ * C_];

// ---------------------------------------------------------------------------
// Zero the scratch each launch (runs BEFORE scatter; also installs the lines
// as dirty-zero in L2 so scatter's atomics hit warm lines). R5-validated.
// ---------------------------------------------------------------------------
__global__ void zero_kernel() {
    const int n4 = (B_ * NY_ * NX_ * C_) / 4;
    float4* p = (float4*)g_scratch;
    for (int idx = blockIdx.x * blockDim.x + threadIdx.x; idx < n4;
         idx += gridDim.x * blockDim.x)
        p[idx] = make_float4(0.f, 0.f, 0.f, 0.f);
}

// Vectorized fire-and-forget reduction (sm_90+): one 16B red per sub-lane.
__device__ __forceinline__ void red_add_v4(float* addr, float4 v) {
    asm volatile("red.global.add.v4.f32 [%0], {%1, %2, %3, %4};"
                 :: "l"(addr), "f"(v.x), "f"(v.y), "f"(v.z), "f"(v.w)
                 : "memory");
}

// ---------------------------------------------------------------------------
// Per-block geometry setup (folded — replaces the 1-block setup kernel that
// measured 5.8us of pure launch/ramp in R8's profile).
// Thread i<8 computes combine = pose_rot @ inv(K) and trans for (b,n)=i into
// SMEM. Exact reference fp32 chain (same fmaf order as the passing kernels).
// ---------------------------------------------------------------------------
__device__ __forceinline__ void compute_geo(const float* __restrict__ intr,
                                            const float* __restrict__ pose,
                                            int i, float* __restrict__ geo12) {
    const float* K = intr + i * 9;
    const float* P = pose + i * 16;

    float a = K[0], bb = K[1], c = K[2];
    float d = K[3], e  = K[4], f = K[5];
    float g = K[6], h  = K[7], ii = K[8];

    float A0 = e * ii - f * h;
    float A1 = f * g  - d * ii;
    float A2 = d * h  - e * g;
    float det = a * A0 + bb * A1 + c * A2;

    float inv[9];
    inv[0] = A0 / det;             inv[1] = (c * h - bb * ii) / det; inv[2] = (bb * f - c * e) / det;
    inv[3] = A1 / det;             inv[4] = (a * ii - c * g) / det;  inv[5] = (c * d - a * f) / det;
    inv[6] = A2 / det;             inv[7] = (bb * g - a * h) / det;  inv[8] = (a * e - bb * d) / det;

    for (int r = 0; r < 3; r++) {
        for (int j = 0; j < 3; j++) {
            float s = P[r * 4 + 0] * inv[0 * 3 + j];
            s = fmaf(P[r * 4 + 1], inv[1 * 3 + j], s);
            s = fmaf(P[r * 4 + 2], inv[2 * 3 + j], s);
            geo12[r * 3 + j] = s;
        }
        geo12[9 + r] = P[r * 4 + 3];
    }
}

// ---------------------------------------------------------------------------
// Scatter: one HALF-warp (16 lanes) per (b,d,h,w) group; sub-lane owns 4
// channels.
// Phase 0: threads 0-7 build the 8 view matrices in SMEM; one barrier.
// Phase 1: compute all 4 view flats (pure ALU — exact reference fp32 chain).
// Phase 2: issue all 4 predicated LDG.128s into independent registers (MLP=4;
//          culled views/depths load nothing).
// Phase 3: register-merge consecutive views hitting the same voxel
//          (data-driven flat==cur check), flush via red.global.add.v4.
// Grid is exactly NG*16/256 = 20160 full blocks (no tail-barrier hazard).
// ---------------------------------------------------------------------------
__global__ void __launch_bounds__(256)
scatter_kernel(const float* __restrict__ x,
               const float* __restrict__ intr,
               const float* __restrict__ pose) {
    __shared__ float s_geo[B_ * N_ * 12];

    if (threadIdx.x < B_ * N_)
        compute_geo(intr, pose, threadIdx.x, s_geo + threadIdx.x * 12);
    __syncthreads();

    int tid   = blockIdx.x * blockDim.x + threadIdx.x;
    int group = tid >> 4;                       // one group per 16 lanes
    int sub   = threadIdx.x & 15;               // channel sub-lane
    const int NG = B_ * D_ * H_ * W_;
    if (group >= NG) return;

    int w = group % W_;
    int t = group / W_;
    int h = t % H_;  t /= H_;
    int d = t % D_;
    int b = t / D_;

    float df = 2.0f + (float)d;                 // ds = arange(2,50,1)
    float u  = (float)w * (479.0f / 59.0f);     // linspace(0, 479, 60)
    float v  = (float)h * (223.0f / 27.0f);     // linspace(0, 223, 28)
    float p0 = u * df, p1 = v * df, p2 = df;

    // ---- Phase 1: flats for all 4 views (no memory traffic) ----
    int flat[N_];
    #pragma unroll
    for (int n = 0; n < N_; n++) {
        const float* G = s_geo + (b * N_ + n) * 12;
        float dx = G[0] * p0; dx = fmaf(G[1], p1, dx); dx = fmaf(G[2], p2, dx);
        float dy = G[3] * p0; dy = fmaf(G[4], p1, dy); dy = fmaf(G[5], p2, dy);
        float dz = G[6] * p0; dz = fmaf(G[7], p1, dz); dz = fmaf(G[8], p2, dz);
        float gxf = dx + G[9];
        float gyf = dy + G[10];
        float gzf = dz + G[11];

        // Truncation toward zero == jnp astype(int32); (-0.5 -> 0 is KEPT in both)
        int gx = (int)(gxf * 4.0f + 96.0f);
        int gy = (int)(gyf * 4.0f + 96.0f);
        int gz = (int)__fdiv_rn(gzf + 10.0f, 20.0f);

        flat[n] = -1;
        if (gx >= 0 && gx < NX_ && gy >= 0 && gy < NY_ && gz >= 0 && gz < 1)
            flat[n] = ((b /*NZ=1*/ + gz) * NY_ + gy) * NX_ + gx;
    }

    // ---- Phase 2: hoisted, predicated, independent LDG.128s (MLP=4) ----
    const float* xb = x
        + ((((size_t)b * N_ + 0) * D_ + d) * H_ + h) * (size_t)(W_ * C_)
        + (size_t)w * C_ + sub * 4;

    float4 xv[N_];
    #pragma unroll
    for (int n = 0; n < N_; n++) {
        if (flat[n] >= 0)
            xv[n] = *(const float4*)(xb + (size_t)n * (D_ * H_ * W_ * C_));
    }

    // ---- Phase 3: merge + flush ----
    int    cur = -1;
    float4 acc = make_float4(0.f, 0.f, 0.f, 0.f);
    #pragma unroll
    for (int n = 0; n < N_; n++) {
        if (flat[n] >= 0) {
            if (flat[n] == cur) {
                acc.x += xv[n].x; acc.y += xv[n].y;
                acc.z += xv[n].z; acc.w += xv[n].w;
            } else {
                if (cur >= 0)
                    red_add_v4(g_scratch + (size_t)cur * C_ + sub * 4, acc);
                cur = flat[n]; acc = xv[n];
            }
        }
    }
    if (cur >= 0)
        red_add_v4(g_scratch + (size_t)cur * C_ + sub * 4, acc);
}

// ---------------------------------------------------------------------------
// Transpose scratch (B,NY,NX,C) -> out (B, C, NY, NX). READ-ONLY on scratch —
// the fused zero-writeback variant stalled the store queue on same-address
// WAR ordering (R11 profile: 32us at issue 4.5%); zeroing lives in its own
// kernel again. float4 reads; float4 coalesced out-stores (4 x 128B segments
// per warp instruction; LDS gather pattern is bank-conflict-free).
// ---------------------------------------------------------------------------
__global__ void transpose_kernel(float* __restrict__ out) {
    __shared__ float s[32][C_ + 1];
    int tile = blockIdx.x;                    // B * NY * (NX/32) = 2304
    int xt = tile % (NX_ / 32);
    int y  = (tile / (NX_ / 32)) % NY_;
    int b  = tile / ((NX_ / 32) * NY_);

    const float4* src = (const float4*)(g_scratch
        + (((size_t)b * NY_ + y) * NX_ + (size_t)xt * 32) * C_);

    int t = threadIdx.x;                      // 256 threads; 512 float4 per tile
    #pragma unroll
    for (int k = 0; k < 2; k++) {
        int i = t + k * 256;
        float4 val = src[i];
        int xx = i >> 4;                      // / (C_/4)
        int cc = (i & 15) << 2;
        s[xx][cc + 0] = val.x; s[xx][cc + 1] = val.y;
        s[xx][cc + 2] = val.z; s[xx][cc + 3] = val.w;
    }
    __syncthreads();

    size_t obase = ((size_t)b * C_) * (NY_ * NX_) + (size_t)y * NX_
                 + (size_t)xt * 32;
    #pragma unroll
    for (int k = 0; k < 2; k++) {
        int p  = t + k * 256;                 // 512 (c, x-quad) pairs
        int x4 = (p & 7) * 4;                 // octet of lanes -> 128B run in x
        int c  = p >> 3;
        float4 v = make_float4(s[x4 + 0][c], s[x4 + 1][c],
                               s[x4 + 2][c], s[x4 + 3][c]);
        *(float4*)(out + obase + (size_t)c * (NY_ * NX_) + x4) = v;
    }
}

// ---------------------------------------------------------------------------
extern "C" void kernel_launch(void* const* d_in, const int* in_sizes, int n_in,
                              void* d_out, int out_size) {
    // Resolve inputs by element count (robust to metadata ordering):
    //   x: B*N*D*H*W*C = 41,287,680   pose: B*N*16 = 128   intrinsics: B*N*9 = 72
    const float* x    = nullptr;
    const float* intr = nullptr;
    const float* pose = nullptr;
    for (int i = 0; i < n_in; i++) {
        if (in_sizes[i] == B_ * N_ * 16)      pose = (const float*)d_in[i];
        else if (in_sizes[i] == B_ * N_ * 9)  intr = (const float*)d_in[i];
        else                                  x    = (const float*)d_in[i];
    }
    float* out = (float*)d_out;

    zero_kernel<<<1184, 256>>>();             // grid-stride, ~8 blocks/SM

    const int ngroups  = B_ * D_ * H_ * W_;      // 322,560 half-warp groups
    const int nthreads = ngroups * 16;           // exactly 20160 blocks of 256
    scatter_kernel<<<nthreads / 256, 256>>>(x, intr, pose);

    transpose_kernel<<<B_ * NY_ * (NX_ / 32), 256>>>(out);
}